// round 6
// baseline (speedup 1.0000x reference)
#include <cuda_runtime.h>
#include <math.h>

#define B_   4096
#define L_   50
#define K_   10
#define LI_  20
#define D_   64
#define C_   10
#define NIP1 50001
#define NSEG 256          // B_/16 segments for the persistent LSTM

typedef unsigned long long ull;

// ---------------- scratch (static device globals; no allocation) -------------
__device__ float g_ju1[NIP1 * 256];   // gate-permuted x@Wih with all biases folded
__device__ float g_jv[NIP1 * D_];
__device__ float g_wc[74 * 256];      // (W1@Wih) gate-permuted
__device__ float g_bc[256];           // b1@Wih + bih + bhh, gate-permuted
__device__ float g_wi[192 * 128];     // interleaved (W2[k][c], W5[k][c])
__device__ float g_hu[B_ * D_];
__device__ float g_s1[K_ * B_];       // transposed [K][B]
__device__ float g_s2[K_ * B_];
__device__ float g_d1[K_ * B_];
__device__ float g_d2[K_ * B_];
__device__ float g_cs[4 * K_];
__device__ int   g_order[B_];
__device__ int   g_ctr;

__device__ __forceinline__ float lrelu(float x) { return x >= 0.f ? x : 0.01f * x; }

// packed f32x2 fma (FFMA2) — only reachable via PTX
#define FMA2(d, a, b, c) \
    asm("fma.rn.f32x2 %0, %1, %2, %3;" : "=l"(d) : "l"(a), "l"(b), "l"(c))
#define PACK_DUP(d, x) \
    asm("mov.b64 %0, {%1, %1};" : "=l"(d) : "f"(x))
#define PACK2(d, lo, hi) \
    asm("mov.b64 %0, {%1, %2};" : "=l"(d) : "f"(lo), "f"(hi))
#define UNPACK2(lo, hi, p) \
    asm("mov.b64 {%0, %1}, %2;" : "=f"(lo), "=f"(hi) : "l"(p))

__device__ __forceinline__ float sigf(float x) {
    return __fdividef(1.f, 1.f + __expf(-x));
}
__device__ __forceinline__ float tanhf_fast(float x) {
    return 1.f - __fdividef(2.f, __expf(2.f * x) + 1.f);
}

// ============================================================================
// K0: combine Wc = W1@Wih (gate-permuted), bc; also build interleaved g_wi.
// Blocks 0..73: Wc rows. Block 74: bc. Blocks 75..170: g_wi.
// ============================================================================
__global__ void k_combine(const float* __restrict__ W1, const float* __restrict__ b1,
                          const float* __restrict__ Wih, const float* __restrict__ bih,
                          const float* __restrict__ bhh,
                          const float* __restrict__ W2, const float* __restrict__ W5) {
    int k = blockIdx.x;
    int tid = threadIdx.x;
    if (k < 74) {
        int jp = tid;
        int c = jp >> 2, g = jp & 3;
        int j = c + 64 * g;
        float s = 0.f;
#pragma unroll
        for (int m = 0; m < 64; m++)
            s = fmaf(W1[k * 64 + m], __ldg(&Wih[m * 256 + j]), s);
        g_wc[k * 256 + jp] = s;
    } else if (k == 74) {
        int jp = tid;
        int c = jp >> 2, g = jp & 3;
        int j = c + 64 * g;
        float s = bih[j] + bhh[j];
#pragma unroll
        for (int m = 0; m < 64; m++)
            s = fmaf(b1[m], __ldg(&Wih[m * 256 + j]), s);
        g_bc[jp] = s;
    } else {
        int idx = (k - 75) * 256 + tid;    // 0 .. 192*128-1
        int kk = idx >> 7, j = idx & 127;
        int c = j >> 1;
        g_wi[idx] = (j & 1) ? W5[kk * 64 + c] : W2[kk * 64 + c];
    }
}

// ============================================================================
// K0b: counting sort of rows by u_items_mask, DESCENDING. Also resets g_ctr.
// ============================================================================
__global__ void k_sort(const int* __restrict__ mask) {
    __shared__ int cnt[64], off[64];
    int tid = threadIdx.x;
    if (tid < 64) cnt[tid] = 0;
    __syncthreads();
    for (int i = tid; i < B_; i += 1024) atomicAdd(&cnt[mask[i]], 1);
    __syncthreads();
    if (tid == 0) {
        g_ctr = 0;
        int run = 0;
        for (int m = 50; m >= 1; m--) { off[m] = run; run += cnt[m]; }
    }
    __syncthreads();
    if (tid < 64) cnt[tid] = 0;
    __syncthreads();
    for (int i = tid; i < B_; i += 1024) {
        int m = mask[i];
        int pos = off[m] + atomicAdd(&cnt[m], 1);
        g_order[pos] = i;
    }
}

// ============================================================================
// K1: g_ju1 = x74 @ Wc + bc, g_jv = x74 @ W3 + b3.
// Weights read via __ldg (L1-resident, ~95KB); smem only holds the x tile.
// 32 rows/block, 256 threads = 32 col-threads x 8 row-groups x 4 rows.
// ============================================================================
#define PRE_SMEM (32 * 76 * 4)

__global__ void __launch_bounds__(256)
k_precompute(const float* __restrict__ item_emb, const float* __restrict__ i_class,
             const float* __restrict__ W3, const float* __restrict__ b3) {
    extern __shared__ float sm[];
    float* xs = sm;                  // 32*76

    int tid = threadIdx.x;
    int c = tid & 31, rgrp = tid >> 5;
    int row0 = blockIdx.x * 32;
    for (int i = tid; i < 32 * 74; i += 256) {
        int rr = i / 74, k = i % 74;
        int row = row0 + rr;
        float v = 0.f;
        if (row < NIP1) v = (k < 64) ? item_emb[row * 64 + k] : i_class[row * 10 + (k - 64)];
        xs[rr * 76 + k] = v;
    }
    __syncthreads();

    ull a[4][4], jv[4];
    {
        const ull* bp = (const ull*)&g_bc[8 * c];
        ull b0 = __ldg(bp), b1v = __ldg(bp + 1), b2v = __ldg(bp + 2), b3v = __ldg(bp + 3);
        ull jb = __ldg((const ull*)&b3[2 * c]);
#pragma unroll
        for (int r = 0; r < 4; r++) {
            a[r][0] = b0; a[r][1] = b1v; a[r][2] = b2v; a[r][3] = b3v;
            jv[r] = jb;
        }
    }
#pragma unroll 2
    for (int k = 0; k < 74; k++) {
        const ulonglong2* wp = (const ulonglong2*)&g_wc[k * 256 + 8 * c];
        ulonglong2 wa = __ldg(wp), wb = __ldg(wp + 1);
        ull w3v = __ldg((const ull*)&W3[k * 64 + 2 * c]);
#pragma unroll
        for (int r = 0; r < 4; r++) {
            float av = xs[(rgrp * 4 + r) * 76 + k];
            ull ad; PACK_DUP(ad, av);
            FMA2(a[r][0], ad, wa.x, a[r][0]);
            FMA2(a[r][1], ad, wa.y, a[r][1]);
            FMA2(a[r][2], ad, wb.x, a[r][2]);
            FMA2(a[r][3], ad, wb.y, a[r][3]);
            FMA2(jv[r], ad, w3v, jv[r]);
        }
    }
#pragma unroll
    for (int r = 0; r < 4; r++) {
        int row = row0 + rgrp * 4 + r;
        if (row < NIP1) {
            ull* o = (ull*)&g_ju1[row * 256 + 8 * c];
            o[0] = a[r][0]; o[1] = a[r][1]; o[2] = a[r][2]; o[3] = a[r][3];
            *(ull*)&g_jv[row * 64 + 2 * c] = jv[r];
        }
    }
}

// ============================================================================
// K2: persistent sorted LSTM, now 2 CTAs/SM (grid 296) for latency hiding.
// ============================================================================
#define LSTM_SMEM ((64*256 + 2*64*20) * 4 + (16*50 + 32) * 4)

__global__ void __launch_bounds__(256, 2)
k_lstm(const int* __restrict__ u_items, const int* __restrict__ u_items_mask,
       const float* __restrict__ Whh) {
    extern __shared__ float sm[];
    float* Wp   = sm;                       // 64*256 gate-permuted Whh
    float* hbuf = Wp + 64 * 256;            // 2 x 64*20
    int*   idxs = (int*)(hbuf + 2 * 64 * 20); // 16*50
    int*   rows_s = idxs + 16 * 50;         // 16
    int*   msk_s  = rows_s + 16;            // 16
    __shared__ int s_seg;

    int tid = threadIdx.x;
    for (int i = tid; i < 64 * 256; i += 256) {
        int k = i >> 8, jp = i & 255;
        Wp[i] = Whh[k * 256 + (jp >> 2) + 64 * (jp & 3)];
    }
    int cell = tid & 63;
    int rg = tid >> 6;
    int abase = rg * 4;

    while (true) {
        __syncthreads();                       // s_seg reuse guard
        if (tid == 0) s_seg = atomicAdd(&g_ctr, 1);
        __syncthreads();
        int seg = s_seg;
        if (seg >= NSEG) break;

        if (tid < 16) {
            int orow = g_order[seg * 16 + tid];
            rows_s[tid] = orow;
            msk_s[tid] = u_items_mask[orow];
        }
        for (int i = tid; i < 64 * 20; i += 256) hbuf[i] = 0.f;  // buf0 = h_{-1}=0
        __syncthreads();
        int maxm = msk_s[0];                   // sorted desc -> first is max
        for (int i = tid; i < 16 * 50; i += 256) {
            int r = i / 50, t = i - r * 50;
            if (t < maxm) idxs[i] = u_items[rows_s[r] * 50 + t];
        }
        int msk[4]; float c_reg[4]; int orw[4];
#pragma unroll
        for (int rr = 0; rr < 4; rr++) {
            msk[rr] = msk_s[abase + rr];
            orw[rr] = rows_s[abase + rr];
            c_reg[rr] = 0.f;
        }
        __syncthreads();

        float4 p[4];
#pragma unroll
        for (int rr = 0; rr < 4; rr++)
            p[rr] = *(const float4*)&g_ju1[idxs[(abase + rr) * 50] * 256 + (cell << 2)];

        for (int t = 0; t < maxm; t++) {
            float* hr = hbuf + (t & 1) * 1280;
            float* hw = hbuf + ((t + 1) & 1) * 1280;

            ull acc[2][4];
            PACK2(acc[0][0], p[0].x, p[1].x);
            PACK2(acc[0][1], p[0].y, p[1].y);
            PACK2(acc[0][2], p[0].z, p[1].z);
            PACK2(acc[0][3], p[0].w, p[1].w);
            PACK2(acc[1][0], p[2].x, p[3].x);
            PACK2(acc[1][1], p[2].y, p[3].y);
            PACK2(acc[1][2], p[2].z, p[3].z);
            PACK2(acc[1][3], p[2].w, p[3].w);

            if (t + 1 < maxm) {
#pragma unroll
                for (int rr = 0; rr < 4; rr++)
                    p[rr] = *(const float4*)&g_ju1[idxs[(abase + rr) * 50 + t + 1] * 256 + (cell << 2)];
            }
#pragma unroll 4
            for (int k = 0; k < 64; k++) {
                float4 wv = *(const float4*)&Wp[k * 256 + (cell << 2)];
                ull w0, w1, w2, w3;
                PACK_DUP(w0, wv.x); PACK_DUP(w1, wv.y);
                PACK_DUP(w2, wv.z); PACK_DUP(w3, wv.w);
                ulonglong2 hp = *(const ulonglong2*)&hr[k * 20 + abase];
                FMA2(acc[0][0], hp.x, w0, acc[0][0]);
                FMA2(acc[0][1], hp.x, w1, acc[0][1]);
                FMA2(acc[0][2], hp.x, w2, acc[0][2]);
                FMA2(acc[0][3], hp.x, w3, acc[0][3]);
                FMA2(acc[1][0], hp.y, w0, acc[1][0]);
                FMA2(acc[1][1], hp.y, w1, acc[1][1]);
                FMA2(acc[1][2], hp.y, w2, acc[1][2]);
                FMA2(acc[1][3], hp.y, w3, acc[1][3]);
            }

#pragma unroll
            for (int rp = 0; rp < 2; rp++) {
                float gi0, gi1, gf0, gf1, gg0, gg1, go0, go1;
                UNPACK2(gi0, gi1, acc[rp][0]);
                UNPACK2(gf0, gf1, acc[rp][1]);
                UNPACK2(gg0, gg1, acc[rp][2]);
                UNPACK2(go0, go1, acc[rp][3]);
#pragma unroll
                for (int half = 0; half < 2; half++) {
                    int rr = 2 * rp + half;
                    float gi = half ? gi1 : gi0;
                    float gf = half ? gf1 : gf0;
                    float gg = half ? gg1 : gg0;
                    float go = half ? go1 : go0;
                    float c = sigf(gf) * c_reg[rr] + sigf(gi) * tanhf_fast(gg);
                    c_reg[rr] = c;
                    float h = sigf(go) * tanhf_fast(c);
                    hw[cell * 20 + abase + rr] = h;
                    if (t == msk[rr] - 1) g_hu[orw[rr] * 64 + cell] = h;
                }
            }
            __syncthreads();
        }
    }
}

// ============================================================================
// K3: per-row user stage. 8 warps = 8 rows per block, grid 512.
// GEMV weights via __ldg from g_wi (L1-resident); smem only small buffers.
// ============================================================================
#define USER_SMEM ((128 + 128 + 8*384) * 4)

__global__ void __launch_bounds__(256)
k_user(const int* __restrict__ users, const int* __restrict__ items,
       const int* __restrict__ u_frids, const int* __restrict__ u_frids_mask,
       const int* __restrict__ u_frids_items, const int* __restrict__ F_i,
       const float* __restrict__ user_emb, const float* __restrict__ item_emb,
       const float* __restrict__ b2,
       const float* __restrict__ W4, const float* __restrict__ b4,
       const float* __restrict__ b5,
       const float* __restrict__ W6, const float* __restrict__ b6,
       const float* __restrict__ lambdas) {
    extern __shared__ float sm[];
    float* W4s = sm;                 // 128
    float* W6s = W4s + 128;          // 128
    float* zz  = W6s + 128;          // 8 * 384

    int tid = threadIdx.x;
    if (tid < 128) W4s[tid] = W4[tid];
    else W6s[tid - 128] = W6[tid - 128];
    __syncthreads();

    int w = tid >> 5, lane = tid & 31;
    int row = blockIdx.x * 8 + w;
    int c0 = lane * 2;
    float l0 = lambdas[0], l1 = lambdas[1], l2 = lambdas[2], l3 = lambdas[3];
    float b4v = b4[0], b6v = b6[0];

    int usr = users[row], itm = items[row];
    float2 u2  = *(const float2*)(user_emb + usr * 64 + c0);
    float2 ie2 = *(const float2*)(item_emb + itm * 64 + c0);
    float2 hu2 = *(const float2*)(g_hu + row * 64 + c0);

    // ---- jv gather for all K friends ----
    float px[K_], py[K_];
#pragma unroll
    for (int k = 0; k < K_; k++) { px[k] = 0.f; py[k] = 0.f; }
    const int* ip = u_frids_items + row * (K_ * LI_);
#pragma unroll
    for (int k = 0; k < K_; k++) {
#pragma unroll
        for (int li = 0; li < LI_; li++) {
            int idx = ip[k * LI_ + li];
            float2 j2 = *(const float2*)(g_jv + idx * 64 + c0);
            px[k] += j2.x; py[k] += j2.y;
        }
    }

    // ---- attention partials (du + 10 friends), interleaved butterfly ----
    float du_p = u2.x * W4s[c0] + u2.y * W4s[c0 + 1];
    float at_p[K_];
#pragma unroll
    for (int k = 0; k < K_; k++) {
        int fid = u_frids[row * K_ + k];
        float2 v2 = *(const float2*)(user_emb + fid * 64 + c0);
        at_p[k] = v2.x * W4s[64 + c0] + v2.y * W4s[65 + c0];
    }
#pragma unroll
    for (int o = 16; o; o >>= 1) {
        du_p += __shfl_xor_sync(0xffffffffu, du_p, o);
#pragma unroll
        for (int k = 0; k < K_; k++) at_p[k] += __shfl_xor_sync(0xffffffffu, at_p[k], o);
    }
    int fm = u_frids_mask[row];
    float at[K_];
#pragma unroll
    for (int k = 0; k < K_; k++) at[k] = lrelu(du_p + at_p[k] + b4v);
    float mx = -1e30f;
#pragma unroll
    for (int k = 0; k < K_; k++) if (k < fm) mx = fmaxf(mx, at[k]);
    float se = 0.f, ev[K_];
#pragma unroll
    for (int k = 0; k < K_; k++) { ev[k] = (k < fm) ? expf(at[k] - mx) : 0.f; se += ev[k]; }
    float inv = 1.f / (se * (float)fm);

    float sux = 0.f, suy = 0.f;
#pragma unroll
    for (int k = 0; k < K_; k++) {
        float wk = ev[k] * inv;   // 0 for masked
        sux = fmaf(wk, px[k], sux);
        suy = fmaf(wk, py[k], suy);
    }

    // ---- fused hui/sui GEMV (weights from L1-resident g_wi) ----
    ull* z = (ull*)(zz + w * 384);
    PACK2(z[c0],       hu2.x, sux);
    PACK2(z[c0 + 1],   hu2.y, suy);
    PACK2(z[64 + c0],     ie2.x, ie2.x);
    PACK2(z[64 + c0 + 1], ie2.y, ie2.y);
    PACK2(z[128 + c0],     hu2.x * ie2.x, sux * ie2.x);
    PACK2(z[128 + c0 + 1], hu2.y * ie2.y, suy * ie2.y);
    __syncwarp();
    ull acc0, acc1;
    PACK2(acc0, b2[c0], b5[c0]);
    PACK2(acc1, b2[c0 + 1], b5[c0 + 1]);
    const ulonglong2* wip = (const ulonglong2*)&g_wi[4 * lane];
#pragma unroll 8
    for (int k = 0; k < 192; k++) {
        ull zk = z[k];
        ulonglong2 wv = __ldg(wip + k * 8);   // k*128 floats = k*8 ulonglong2
        FMA2(acc0, zk, wv.x, acc0);
        FMA2(acc1, zk, wv.y, acc1);
    }
    float huix, suix, huiy, suiy;
    UNPACK2(huix, suix, acc0);
    UNPACK2(huiy, suiy, acc1);

    float zsx = l0 * hu2.x + l1 * huix + l2 * sux + l3 * suix;
    float zsy = l0 * hu2.y + l1 * huiy + l2 * suy + l3 * suiy;

    // ---- di + F_i phase ----
    float di_p = ie2.x * W6s[c0] + ie2.y * W6s[c0 + 1];
#pragma unroll
    for (int o = 16; o; o >>= 1) di_p += __shfl_xor_sync(0xffffffffu, di_p, o);

#pragma unroll
    for (int s = 0; s < 2; s++) {
        float sp[K_], dp[K_];
#pragma unroll
        for (int k = 0; k < K_; k++) {
            int fi = F_i[(row * 2 + s) * K_ + k];
            float2 f2 = *(const float2*)(item_emb + fi * 64 + c0);
            sp[k] = f2.x * W6s[64 + c0] + f2.y * W6s[65 + c0];
            dp[k] = f2.x * zsx + f2.y * zsy;
        }
#pragma unroll
        for (int o = 16; o; o >>= 1) {
#pragma unroll
            for (int k = 0; k < K_; k++) {
                sp[k] += __shfl_xor_sync(0xffffffffu, sp[k], o);
                dp[k] += __shfl_xor_sync(0xffffffffu, dp[k], o);
            }
        }
        if (lane == 0) {
            float* spo = s ? g_s2 : g_s1;
            float* dpo = s ? g_d2 : g_d1;
#pragma unroll
            for (int k = 0; k < K_; k++) {
                spo[k * B_ + row] = lrelu(di_p + sp[k] + b6v);   // transposed [K][B]
                dpo[k * B_ + row] = dp[k];
            }
        }
    }
}

// ============================================================================
// K4: per-column softmax stats (online), 20 blocks x 1024 threads.
// s arrays are [K][B] -> fully coalesced reads.
// ============================================================================
__global__ void k_cstat() {
    int sel = blockIdx.x / K_;
    int k = blockIdx.x % K_;
    const float* s = (sel ? g_s2 : g_s1) + k * B_;
    __shared__ float rm[1024], rs[1024];
    int tid = threadIdx.x;
    float m = -1e30f, acc = 0.f;
    for (int i = tid; i < B_; i += 1024) {
        float x = s[i];
        float nm = fmaxf(m, x);
        acc = acc * expf(m - nm) + expf(x - nm);
        m = nm;
    }
    rm[tid] = m; rs[tid] = acc;
    __syncthreads();
    for (int o = 512; o; o >>= 1) {
        if (tid < o) {
            float m2 = rm[tid + o], s2v = rs[tid + o];
            float nm = fmaxf(rm[tid], m2);
            rs[tid] = rs[tid] * expf(rm[tid] - nm) + s2v * expf(m2 - nm);
            rm[tid] = nm;
        }
        __syncthreads();
    }
    if (tid == 0) { g_cs[sel * 2 * K_ + k] = rm[0]; g_cs[sel * 2 * K_ + K_ + k] = rs[0]; }
}

// ============================================================================
// K5: final S + sigmoid (coalesced [K][B] reads)
// ============================================================================
__global__ void k_final(const float* __restrict__ alpha, float* __restrict__ out) {
    int b = blockIdx.x * 256 + threadIdx.x;
    float a = alpha[0];
    float S1 = 0.f, S2 = 0.f;
#pragma unroll
    for (int k = 0; k < K_; k++) {
        S1 += expf(g_s1[k * B_ + b] - g_cs[k]) / g_cs[K_ + k] * g_d1[k * B_ + b];
        S2 += expf(g_s2[k * B_ + b] - g_cs[2 * K_ + k]) / g_cs[3 * K_ + k] * g_d2[k * B_ + b];
    }
    float S = a * S1 + (1.f - a) * S2;
    out[b] = 1.f / (1.f + expf(-S));
}

// ============================================================================
extern "C" void kernel_launch(void* const* d_in, const int* in_sizes, int n_in,
                              void* d_out, int out_size) {
    const int*   users        = (const int*)d_in[0];
    const int*   items        = (const int*)d_in[1];
    const int*   u_items      = (const int*)d_in[2];
    const int*   u_items_mask = (const int*)d_in[3];
    const int*   u_frids      = (const int*)d_in[4];
    const int*   u_frids_mask = (const int*)d_in[5];
    const int*   u_frids_items= (const int*)d_in[6];
    const int*   F_i          = (const int*)d_in[7];
    const float* user_emb     = (const float*)d_in[8];
    const float* item_emb     = (const float*)d_in[9];
    const float* i_class      = (const float*)d_in[10];
    const float* W1  = (const float*)d_in[11];
    const float* b1  = (const float*)d_in[12];
    const float* Wih = (const float*)d_in[13];
    const float* Whh = (const float*)d_in[14];
    const float* bih = (const float*)d_in[15];
    const float* bhh = (const float*)d_in[16];
    const float* W2  = (const float*)d_in[17];
    const float* b2  = (const float*)d_in[18];
    const float* W3  = (const float*)d_in[19];
    const float* b3  = (const float*)d_in[20];
    const float* W4  = (const float*)d_in[21];
    const float* b4  = (const float*)d_in[22];
    const float* W5  = (const float*)d_in[23];
    const float* b5  = (const float*)d_in[24];
    const float* W6  = (const float*)d_in[25];
    const float* b6  = (const float*)d_in[26];
    const float* alpha   = (const float*)d_in[27];
    const float* lambdas = (const float*)d_in[28];

    cudaFuncSetAttribute(k_precompute, cudaFuncAttributeMaxDynamicSharedMemorySize, PRE_SMEM);
    cudaFuncSetAttribute(k_lstm, cudaFuncAttributeMaxDynamicSharedMemorySize, LSTM_SMEM);
    cudaFuncSetAttribute(k_user, cudaFuncAttributeMaxDynamicSharedMemorySize, USER_SMEM);

    k_combine<<<171, 256>>>(W1, b1, Wih, bih, bhh, W2, W5);
    k_sort<<<1, 1024>>>(u_items_mask);
    k_precompute<<<(NIP1 + 31) / 32, 256, PRE_SMEM>>>(item_emb, i_class, W3, b3);
    k_lstm<<<296, 256, LSTM_SMEM>>>(u_items, u_items_mask, Whh);
    k_user<<<B_ / 8, 256, USER_SMEM>>>(users, items, u_frids, u_frids_mask,
                                       u_frids_items, F_i, user_emb, item_emb,
                                       b2, W4, b4, b5, W6, b6, lambdas);
    k_cstat<<<2 * K_, 1024>>>();
    k_final<<<B_ / 256, 256>>>(alpha, (float*)d_out);
}

// round 7
// speedup vs baseline: 1.2514x; 1.2514x over previous
#include <cuda_runtime.h>
#include <math.h>

#define B_   4096
#define L_   50
#define K_   10
#define LI_  20
#define D_   64
#define C_   10
#define NIP1 50001
#define NSEG 256          // B_/16 segments for the persistent LSTM

typedef unsigned long long ull;

// ---------------- scratch (static device globals; no allocation) -------------
__device__ float g_ju1[NIP1 * 256];   // gate-permuted x@Wih with all biases folded
__device__ float g_jv[NIP1 * D_];
__device__ float g_wc[74 * 256];      // (W1@Wih) gate-permuted
__device__ float g_bc[256];           // b1@Wih + bih + bhh, gate-permuted
__device__ float g_wi[192 * 128];     // interleaved (W2[k][c], W5[k][c])
__device__ float g_hu[B_ * D_];
__device__ float g_s1[K_ * B_];       // transposed [K][B]
__device__ float g_s2[K_ * B_];
__device__ float g_d1[K_ * B_];
__device__ float g_d2[K_ * B_];
__device__ float g_cs[4 * K_];
__device__ int   g_order[B_];
__device__ int   g_ctr;

__device__ __forceinline__ float lrelu(float x) { return x >= 0.f ? x : 0.01f * x; }

// packed f32x2 fma (FFMA2) — only reachable via PTX
#define FMA2(d, a, b, c) \
    asm("fma.rn.f32x2 %0, %1, %2, %3;" : "=l"(d) : "l"(a), "l"(b), "l"(c))
#define PACK_DUP(d, x) \
    asm("mov.b64 %0, {%1, %1};" : "=l"(d) : "f"(x))
#define PACK2(d, lo, hi) \
    asm("mov.b64 %0, {%1, %2};" : "=l"(d) : "f"(lo), "f"(hi))
#define UNPACK2(lo, hi, p) \
    asm("mov.b64 {%0, %1}, %2;" : "=f"(lo), "=f"(hi) : "l"(p))

__device__ __forceinline__ float sigf(float x) {
    return __fdividef(1.f, 1.f + __expf(-x));
}
__device__ __forceinline__ float tanhf_fast(float x) {
    return 1.f - __fdividef(2.f, __expf(2.f * x) + 1.f);
}

// ============================================================================
// K0: combine Wc = W1@Wih (gate-permuted), bc; also build interleaved g_wi.
// Blocks 0..73: Wc rows. Block 74: bc. Blocks 75..170: g_wi.
// ============================================================================
__global__ void k_combine(const float* __restrict__ W1, const float* __restrict__ b1,
                          const float* __restrict__ Wih, const float* __restrict__ bih,
                          const float* __restrict__ bhh,
                          const float* __restrict__ W2, const float* __restrict__ W5) {
    int k = blockIdx.x;
    int tid = threadIdx.x;
    if (k < 74) {
        int jp = tid;
        int c = jp >> 2, g = jp & 3;
        int j = c + 64 * g;
        float s = 0.f;
#pragma unroll
        for (int m = 0; m < 64; m++)
            s = fmaf(W1[k * 64 + m], __ldg(&Wih[m * 256 + j]), s);
        g_wc[k * 256 + jp] = s;
    } else if (k == 74) {
        int jp = tid;
        int c = jp >> 2, g = jp & 3;
        int j = c + 64 * g;
        float s = bih[j] + bhh[j];
#pragma unroll
        for (int m = 0; m < 64; m++)
            s = fmaf(b1[m], __ldg(&Wih[m * 256 + j]), s);
        g_bc[jp] = s;
    } else {
        int idx = (k - 75) * 256 + tid;    // 0 .. 192*128-1
        int kk = idx >> 7, j = idx & 127;
        int c = j >> 1;
        g_wi[idx] = (j & 1) ? W5[kk * 64 + c] : W2[kk * 64 + c];
    }
}

// ============================================================================
// K0b: counting sort of rows by u_items_mask, DESCENDING. Also resets g_ctr.
// ============================================================================
__global__ void k_sort(const int* __restrict__ mask) {
    __shared__ int cnt[64], off[64];
    int tid = threadIdx.x;
    if (tid < 64) cnt[tid] = 0;
    __syncthreads();
    for (int i = tid; i < B_; i += 1024) atomicAdd(&cnt[mask[i]], 1);
    __syncthreads();
    if (tid == 0) {
        g_ctr = 0;
        int run = 0;
        for (int m = 50; m >= 1; m--) { off[m] = run; run += cnt[m]; }
    }
    __syncthreads();
    if (tid < 64) cnt[tid] = 0;
    __syncthreads();
    for (int i = tid; i < B_; i += 1024) {
        int m = mask[i];
        int pos = off[m] + atomicAdd(&cnt[m], 1);
        g_order[pos] = i;
    }
}

// ============================================================================
// K1: g_ju1 = x74 @ Wc + bc, g_jv = x74 @ W3 + b3.
// Weights read via __ldg (L1-resident, ~95KB); smem only holds the x tile.
// ============================================================================
#define PRE_SMEM (32 * 76 * 4)

__global__ void __launch_bounds__(256)
k_precompute(const float* __restrict__ item_emb, const float* __restrict__ i_class,
             const float* __restrict__ W3, const float* __restrict__ b3) {
    extern __shared__ float sm[];
    float* xs = sm;                  // 32*76

    int tid = threadIdx.x;
    int c = tid & 31, rgrp = tid >> 5;
    int row0 = blockIdx.x * 32;
    for (int i = tid; i < 32 * 74; i += 256) {
        int rr = i / 74, k = i % 74;
        int row = row0 + rr;
        float v = 0.f;
        if (row < NIP1) v = (k < 64) ? item_emb[row * 64 + k] : i_class[row * 10 + (k - 64)];
        xs[rr * 76 + k] = v;
    }
    __syncthreads();

    ull a[4][4], jv[4];
    {
        const ull* bp = (const ull*)&g_bc[8 * c];
        ull b0 = __ldg(bp), b1v = __ldg(bp + 1), b2v = __ldg(bp + 2), b3v = __ldg(bp + 3);
        ull jb = __ldg((const ull*)&b3[2 * c]);
#pragma unroll
        for (int r = 0; r < 4; r++) {
            a[r][0] = b0; a[r][1] = b1v; a[r][2] = b2v; a[r][3] = b3v;
            jv[r] = jb;
        }
    }
#pragma unroll 2
    for (int k = 0; k < 74; k++) {
        const ulonglong2* wp = (const ulonglong2*)&g_wc[k * 256 + 8 * c];
        ulonglong2 wa = __ldg(wp), wb = __ldg(wp + 1);
        ull w3v = __ldg((const ull*)&W3[k * 64 + 2 * c]);
#pragma unroll
        for (int r = 0; r < 4; r++) {
            float av = xs[(rgrp * 4 + r) * 76 + k];
            ull ad; PACK_DUP(ad, av);
            FMA2(a[r][0], ad, wa.x, a[r][0]);
            FMA2(a[r][1], ad, wa.y, a[r][1]);
            FMA2(a[r][2], ad, wb.x, a[r][2]);
            FMA2(a[r][3], ad, wb.y, a[r][3]);
            FMA2(jv[r], ad, w3v, jv[r]);
        }
    }
#pragma unroll
    for (int r = 0; r < 4; r++) {
        int row = row0 + rgrp * 4 + r;
        if (row < NIP1) {
            ull* o = (ull*)&g_ju1[row * 256 + 8 * c];
            o[0] = a[r][0]; o[1] = a[r][1]; o[2] = a[r][2]; o[3] = a[r][3];
            *(ull*)&g_jv[row * 64 + 2 * c] = jv[r];
        }
    }
}

// ============================================================================
// K2: persistent sorted LSTM — ROUND-5 VALIDATED CONFIG (148 CTAs, 1/SM).
// 16-row segments (sorted by mask desc) pulled via atomic counter (LPT).
// ============================================================================
#define LSTM_SMEM ((64*256 + 2*64*20) * 4 + (16*50 + 32) * 4)

__global__ void __launch_bounds__(256, 1)
k_lstm(const int* __restrict__ u_items, const int* __restrict__ u_items_mask,
       const float* __restrict__ Whh) {
    extern __shared__ float sm[];
    float* Wp   = sm;                       // 64*256 gate-permuted Whh
    float* hbuf = Wp + 64 * 256;            // 2 x 64*20
    int*   idxs = (int*)(hbuf + 2 * 64 * 20); // 16*50
    int*   rows_s = idxs + 16 * 50;         // 16
    int*   msk_s  = rows_s + 16;            // 16
    __shared__ int s_seg;

    int tid = threadIdx.x;
    for (int i = tid; i < 64 * 256; i += 256) {
        int k = i >> 8, jp = i & 255;
        Wp[i] = Whh[k * 256 + (jp >> 2) + 64 * (jp & 3)];
    }
    int cell = tid & 63;
    int rg = tid >> 6;
    int abase = rg * 4;

    while (true) {
        __syncthreads();                       // s_seg reuse guard
        if (tid == 0) s_seg = atomicAdd(&g_ctr, 1);
        __syncthreads();
        int seg = s_seg;
        if (seg >= NSEG) break;

        if (tid < 16) {
            int orow = g_order[seg * 16 + tid];
            rows_s[tid] = orow;
            msk_s[tid] = u_items_mask[orow];
        }
        for (int i = tid; i < 64 * 20; i += 256) hbuf[i] = 0.f;  // buf0 = h_{-1}=0
        __syncthreads();
        int maxm = msk_s[0];                   // sorted desc -> first is max
        for (int i = tid; i < 16 * 50; i += 256) {
            int r = i / 50, t = i - r * 50;
            if (t < maxm) idxs[i] = u_items[rows_s[r] * 50 + t];
        }
        int msk[4]; float c_reg[4]; int orw[4];
#pragma unroll
        for (int rr = 0; rr < 4; rr++) {
            msk[rr] = msk_s[abase + rr];
            orw[rr] = rows_s[abase + rr];
            c_reg[rr] = 0.f;
        }
        __syncthreads();

        float4 p[4];
#pragma unroll
        for (int rr = 0; rr < 4; rr++)
            p[rr] = *(const float4*)&g_ju1[idxs[(abase + rr) * 50] * 256 + (cell << 2)];

        for (int t = 0; t < maxm; t++) {
            float* hr = hbuf + (t & 1) * 1280;
            float* hw = hbuf + ((t + 1) & 1) * 1280;

            ull acc[2][4];
            PACK2(acc[0][0], p[0].x, p[1].x);
            PACK2(acc[0][1], p[0].y, p[1].y);
            PACK2(acc[0][2], p[0].z, p[1].z);
            PACK2(acc[0][3], p[0].w, p[1].w);
            PACK2(acc[1][0], p[2].x, p[3].x);
            PACK2(acc[1][1], p[2].y, p[3].y);
            PACK2(acc[1][2], p[2].z, p[3].z);
            PACK2(acc[1][3], p[2].w, p[3].w);

            if (t + 1 < maxm) {
#pragma unroll
                for (int rr = 0; rr < 4; rr++)
                    p[rr] = *(const float4*)&g_ju1[idxs[(abase + rr) * 50 + t + 1] * 256 + (cell << 2)];
            }
#pragma unroll 4
            for (int k = 0; k < 64; k++) {
                float4 wv = *(const float4*)&Wp[k * 256 + (cell << 2)];
                ull w0, w1, w2, w3;
                PACK_DUP(w0, wv.x); PACK_DUP(w1, wv.y);
                PACK_DUP(w2, wv.z); PACK_DUP(w3, wv.w);
                ulonglong2 hp = *(const ulonglong2*)&hr[k * 20 + abase];
                FMA2(acc[0][0], hp.x, w0, acc[0][0]);
                FMA2(acc[0][1], hp.x, w1, acc[0][1]);
                FMA2(acc[0][2], hp.x, w2, acc[0][2]);
                FMA2(acc[0][3], hp.x, w3, acc[0][3]);
                FMA2(acc[1][0], hp.y, w0, acc[1][0]);
                FMA2(acc[1][1], hp.y, w1, acc[1][1]);
                FMA2(acc[1][2], hp.y, w2, acc[1][2]);
                FMA2(acc[1][3], hp.y, w3, acc[1][3]);
            }

#pragma unroll
            for (int rp = 0; rp < 2; rp++) {
                float gi0, gi1, gf0, gf1, gg0, gg1, go0, go1;
                UNPACK2(gi0, gi1, acc[rp][0]);
                UNPACK2(gf0, gf1, acc[rp][1]);
                UNPACK2(gg0, gg1, acc[rp][2]);
                UNPACK2(go0, go1, acc[rp][3]);
#pragma unroll
                for (int half = 0; half < 2; half++) {
                    int rr = 2 * rp + half;
                    float gi = half ? gi1 : gi0;
                    float gf = half ? gf1 : gf0;
                    float gg = half ? gg1 : gg0;
                    float go = half ? go1 : go0;
                    float c = sigf(gf) * c_reg[rr] + sigf(gi) * tanhf_fast(gg);
                    c_reg[rr] = c;
                    float h = sigf(go) * tanhf_fast(c);
                    hw[cell * 20 + abase + rr] = h;
                    if (t == msk[rr] - 1) g_hu[orw[rr] * 64 + cell] = h;
                }
            }
            __syncthreads();
        }
    }
}

// ============================================================================
// K3: per-row user stage. 8 warps = 8 rows per block, grid 512.
// GEMV weights via __ldg from g_wi (L1-resident). FIXED row stride (k*32).
// ============================================================================
#define USER_SMEM ((128 + 128 + 8*384) * 4)

__global__ void __launch_bounds__(256)
k_user(const int* __restrict__ users, const int* __restrict__ items,
       const int* __restrict__ u_frids, const int* __restrict__ u_frids_mask,
       const int* __restrict__ u_frids_items, const int* __restrict__ F_i,
       const float* __restrict__ user_emb, const float* __restrict__ item_emb,
       const float* __restrict__ b2,
       const float* __restrict__ W4, const float* __restrict__ b4,
       const float* __restrict__ b5,
       const float* __restrict__ W6, const float* __restrict__ b6,
       const float* __restrict__ lambdas) {
    extern __shared__ float sm[];
    float* W4s = sm;                 // 128
    float* W6s = W4s + 128;          // 128
    float* zz  = W6s + 128;          // 8 * 384

    int tid = threadIdx.x;
    if (tid < 128) W4s[tid] = W4[tid];
    else W6s[tid - 128] = W6[tid - 128];
    __syncthreads();

    int w = tid >> 5, lane = tid & 31;
    int row = blockIdx.x * 8 + w;
    int c0 = lane * 2;
    float l0 = lambdas[0], l1 = lambdas[1], l2 = lambdas[2], l3 = lambdas[3];
    float b4v = b4[0], b6v = b6[0];

    int usr = users[row], itm = items[row];
    float2 u2  = *(const float2*)(user_emb + usr * 64 + c0);
    float2 ie2 = *(const float2*)(item_emb + itm * 64 + c0);
    float2 hu2 = *(const float2*)(g_hu + row * 64 + c0);

    // ---- jv gather for all K friends ----
    float px[K_], py[K_];
#pragma unroll
    for (int k = 0; k < K_; k++) { px[k] = 0.f; py[k] = 0.f; }
    const int* ip = u_frids_items + row * (K_ * LI_);
#pragma unroll
    for (int k = 0; k < K_; k++) {
#pragma unroll
        for (int li = 0; li < LI_; li++) {
            int idx = ip[k * LI_ + li];
            float2 j2 = *(const float2*)(g_jv + idx * 64 + c0);
            px[k] += j2.x; py[k] += j2.y;
        }
    }

    // ---- attention partials (du + 10 friends), interleaved butterfly ----
    float du_p = u2.x * W4s[c0] + u2.y * W4s[c0 + 1];
    float at_p[K_];
#pragma unroll
    for (int k = 0; k < K_; k++) {
        int fid = u_frids[row * K_ + k];
        float2 v2 = *(const float2*)(user_emb + fid * 64 + c0);
        at_p[k] = v2.x * W4s[64 + c0] + v2.y * W4s[65 + c0];
    }
#pragma unroll
    for (int o = 16; o; o >>= 1) {
        du_p += __shfl_xor_sync(0xffffffffu, du_p, o);
#pragma unroll
        for (int k = 0; k < K_; k++) at_p[k] += __shfl_xor_sync(0xffffffffu, at_p[k], o);
    }
    int fm = u_frids_mask[row];
    float at[K_];
#pragma unroll
    for (int k = 0; k < K_; k++) at[k] = lrelu(du_p + at_p[k] + b4v);
    float mx = -1e30f;
#pragma unroll
    for (int k = 0; k < K_; k++) if (k < fm) mx = fmaxf(mx, at[k]);
    float se = 0.f, ev[K_];
#pragma unroll
    for (int k = 0; k < K_; k++) { ev[k] = (k < fm) ? expf(at[k] - mx) : 0.f; se += ev[k]; }
    float inv = 1.f / (se * (float)fm);

    float sux = 0.f, suy = 0.f;
#pragma unroll
    for (int k = 0; k < K_; k++) {
        float wk = ev[k] * inv;   // 0 for masked
        sux = fmaf(wk, px[k], sux);
        suy = fmaf(wk, py[k], suy);
    }

    // ---- fused hui/sui GEMV (weights from L1-resident g_wi) ----
    ull* z = (ull*)(zz + w * 384);
    PACK2(z[c0],       hu2.x, sux);
    PACK2(z[c0 + 1],   hu2.y, suy);
    PACK2(z[64 + c0],     ie2.x, ie2.x);
    PACK2(z[64 + c0 + 1], ie2.y, ie2.y);
    PACK2(z[128 + c0],     hu2.x * ie2.x, sux * ie2.x);
    PACK2(z[128 + c0 + 1], hu2.y * ie2.y, suy * ie2.y);
    __syncwarp();
    ull acc0, acc1;
    PACK2(acc0, b2[c0], b5[c0]);
    PACK2(acc1, b2[c0 + 1], b5[c0 + 1]);
    const ulonglong2* wip = (const ulonglong2*)&g_wi[4 * lane];
#pragma unroll 8
    for (int k = 0; k < 192; k++) {
        ull zk = z[k];
        ulonglong2 wv = __ldg(wip + k * 32);   // row = 128 floats = 32 ulonglong2
        FMA2(acc0, zk, wv.x, acc0);
        FMA2(acc1, zk, wv.y, acc1);
    }
    float huix, suix, huiy, suiy;
    UNPACK2(huix, suix, acc0);
    UNPACK2(huiy, suiy, acc1);

    float zsx = l0 * hu2.x + l1 * huix + l2 * sux + l3 * suix;
    float zsy = l0 * hu2.y + l1 * huiy + l2 * suy + l3 * suiy;

    // ---- di + F_i phase ----
    float di_p = ie2.x * W6s[c0] + ie2.y * W6s[c0 + 1];
#pragma unroll
    for (int o = 16; o; o >>= 1) di_p += __shfl_xor_sync(0xffffffffu, di_p, o);

#pragma unroll
    for (int s = 0; s < 2; s++) {
        float sp[K_], dp[K_];
#pragma unroll
        for (int k = 0; k < K_; k++) {
            int fi = F_i[(row * 2 + s) * K_ + k];
            float2 f2 = *(const float2*)(item_emb + fi * 64 + c0);
            sp[k] = f2.x * W6s[64 + c0] + f2.y * W6s[65 + c0];
            dp[k] = f2.x * zsx + f2.y * zsy;
        }
#pragma unroll
        for (int o = 16; o; o >>= 1) {
#pragma unroll
            for (int k = 0; k < K_; k++) {
                sp[k] += __shfl_xor_sync(0xffffffffu, sp[k], o);
                dp[k] += __shfl_xor_sync(0xffffffffu, dp[k], o);
            }
        }
        if (lane == 0) {
            float* spo = s ? g_s2 : g_s1;
            float* dpo = s ? g_d2 : g_d1;
#pragma unroll
            for (int k = 0; k < K_; k++) {
                spo[k * B_ + row] = lrelu(di_p + sp[k] + b6v);   // transposed [K][B]
                dpo[k * B_ + row] = dp[k];
            }
        }
    }
}

// ============================================================================
// K4: per-column softmax stats (online), 20 blocks x 1024 threads, coalesced.
// ============================================================================
__global__ void k_cstat() {
    int sel = blockIdx.x / K_;
    int k = blockIdx.x % K_;
    const float* s = (sel ? g_s2 : g_s1) + k * B_;
    __shared__ float rm[1024], rs[1024];
    int tid = threadIdx.x;
    float m = -1e30f, acc = 0.f;
    for (int i = tid; i < B_; i += 1024) {
        float x = s[i];
        float nm = fmaxf(m, x);
        acc = acc * expf(m - nm) + expf(x - nm);
        m = nm;
    }
    rm[tid] = m; rs[tid] = acc;
    __syncthreads();
    for (int o = 512; o; o >>= 1) {
        if (tid < o) {
            float m2 = rm[tid + o], s2v = rs[tid + o];
            float nm = fmaxf(rm[tid], m2);
            rs[tid] = rs[tid] * expf(rm[tid] - nm) + s2v * expf(m2 - nm);
            rm[tid] = nm;
        }
        __syncthreads();
    }
    if (tid == 0) { g_cs[sel * 2 * K_ + k] = rm[0]; g_cs[sel * 2 * K_ + K_ + k] = rs[0]; }
}

// ============================================================================
// K5: final S + sigmoid (coalesced [K][B] reads)
// ============================================================================
__global__ void k_final(const float* __restrict__ alpha, float* __restrict__ out) {
    int b = blockIdx.x * 256 + threadIdx.x;
    float a = alpha[0];
    float S1 = 0.f, S2 = 0.f;
#pragma unroll
    for (int k = 0; k < K_; k++) {
        S1 += expf(g_s1[k * B_ + b] - g_cs[k]) / g_cs[K_ + k] * g_d1[k * B_ + b];
        S2 += expf(g_s2[k * B_ + b] - g_cs[2 * K_ + k]) / g_cs[3 * K_ + k] * g_d2[k * B_ + b];
    }
    float S = a * S1 + (1.f - a) * S2;
    out[b] = 1.f / (1.f + expf(-S));
}

// ============================================================================
extern "C" void kernel_launch(void* const* d_in, const int* in_sizes, int n_in,
                              void* d_out, int out_size) {
    const int*   users        = (const int*)d_in[0];
    const int*   items        = (const int*)d_in[1];
    const int*   u_items      = (const int*)d_in[2];
    const int*   u_items_mask = (const int*)d_in[3];
    const int*   u_frids      = (const int*)d_in[4];
    const int*   u_frids_mask = (const int*)d_in[5];
    const int*   u_frids_items= (const int*)d_in[6];
    const int*   F_i          = (const int*)d_in[7];
    const float* user_emb     = (const float*)d_in[8];
    const float* item_emb     = (const float*)d_in[9];
    const float* i_class      = (const float*)d_in[10];
    const float* W1  = (const float*)d_in[11];
    const float* b1  = (const float*)d_in[12];
    const float* Wih = (const float*)d_in[13];
    const float* Whh = (const float*)d_in[14];
    const float* bih = (const float*)d_in[15];
    const float* bhh = (const float*)d_in[16];
    const float* W2  = (const float*)d_in[17];
    const float* b2  = (const float*)d_in[18];
    const float* W3  = (const float*)d_in[19];
    const float* b3  = (const float*)d_in[20];
    const float* W4  = (const float*)d_in[21];
    const float* b4  = (const float*)d_in[22];
    const float* W5  = (const float*)d_in[23];
    const float* b5  = (const float*)d_in[24];
    const float* W6  = (const float*)d_in[25];
    const float* b6  = (const float*)d_in[26];
    const float* alpha   = (const float*)d_in[27];
    const float* lambdas = (const float*)d_in[28];

    cudaFuncSetAttribute(k_precompute, cudaFuncAttributeMaxDynamicSharedMemorySize, PRE_SMEM);
    cudaFuncSetAttribute(k_lstm, cudaFuncAttributeMaxDynamicSharedMemorySize, LSTM_SMEM);
    cudaFuncSetAttribute(k_user, cudaFuncAttributeMaxDynamicSharedMemorySize, USER_SMEM);

    k_combine<<<171, 256>>>(W1, b1, Wih, bih, bhh, W2, W5);
    k_sort<<<1, 1024>>>(u_items_mask);
    k_precompute<<<(NIP1 + 31) / 32, 256, PRE_SMEM>>>(item_emb, i_class, W3, b3);
    k_lstm<<<148, 256, LSTM_SMEM>>>(u_items, u_items_mask, Whh);
    k_user<<<B_ / 8, 256, USER_SMEM>>>(users, items, u_frids, u_frids_mask,
                                       u_frids_items, F_i, user_emb, item_emb,
                                       b2, W4, b4, b5, W6, b6, lambdas);
    k_cstat<<<2 * K_, 1024>>>();
    k_final<<<B_ / 256, 256>>>(alpha, (float*)d_out);
}

// round 8
// speedup vs baseline: 1.2827x; 1.0250x over previous
#include <cuda_runtime.h>
#include <math.h>

#define B_   4096
#define L_   50
#define K_   10
#define LI_  20
#define D_   64
#define C_   10
#define NIP1 50001

typedef unsigned long long ull;

// ---------------- scratch (static device globals; no allocation) -------------
__device__ float g_ju1[NIP1 * 256];   // gate-permuted x@Wih with all biases folded
__device__ float g_jv[NIP1 * D_];
__device__ float g_wc[74 * 256];      // (W1@Wih) gate-permuted
__device__ float g_bc[256];           // b1@Wih + bih + bhh, gate-permuted
__device__ float g_wi[192 * 128];     // interleaved (W2[k][c], W5[k][c])
__device__ float g_hu[B_ * D_];
__device__ float g_s1[K_ * B_];       // transposed [K][B]
__device__ float g_s2[K_ * B_];
__device__ float g_d1[K_ * B_];
__device__ float g_d2[K_ * B_];
__device__ float g_cs[4 * K_];
__device__ int   g_order[B_];
__device__ int   g_ctr;

__device__ __forceinline__ float lrelu(float x) { return x >= 0.f ? x : 0.01f * x; }

// packed f32x2 fma (FFMA2) — only reachable via PTX
#define FMA2(d, a, b, c) \
    asm("fma.rn.f32x2 %0, %1, %2, %3;" : "=l"(d) : "l"(a), "l"(b), "l"(c))
#define PACK_DUP(d, x) \
    asm("mov.b64 %0, {%1, %1};" : "=l"(d) : "f"(x))
#define PACK2(d, lo, hi) \
    asm("mov.b64 %0, {%1, %2};" : "=l"(d) : "f"(lo), "f"(hi))
#define UNPACK2(lo, hi, p) \
    asm("mov.b64 {%0, %1}, %2;" : "=f"(lo), "=f"(hi) : "l"(p))

__device__ __forceinline__ float sigf(float x) {
    return __fdividef(1.f, 1.f + __expf(-x));
}
__device__ __forceinline__ float tanhf_fast(float x) {
    return 1.f - __fdividef(2.f, __expf(2.f * x) + 1.f);
}

// ============================================================================
// K0: combine Wc = W1@Wih (gate-permuted), bc; also build interleaved g_wi.
// ============================================================================
__global__ void k_combine(const float* __restrict__ W1, const float* __restrict__ b1,
                          const float* __restrict__ Wih, const float* __restrict__ bih,
                          const float* __restrict__ bhh,
                          const float* __restrict__ W2, const float* __restrict__ W5) {
    int k = blockIdx.x;
    int tid = threadIdx.x;
    if (k < 74) {
        int jp = tid;
        int c = jp >> 2, g = jp & 3;
        int j = c + 64 * g;
        float s = 0.f;
#pragma unroll
        for (int m = 0; m < 64; m++)
            s = fmaf(W1[k * 64 + m], __ldg(&Wih[m * 256 + j]), s);
        g_wc[k * 256 + jp] = s;
    } else if (k == 74) {
        int jp = tid;
        int c = jp >> 2, g = jp & 3;
        int j = c + 64 * g;
        float s = bih[j] + bhh[j];
#pragma unroll
        for (int m = 0; m < 64; m++)
            s = fmaf(b1[m], __ldg(&Wih[m * 256 + j]), s);
        g_bc[jp] = s;
    } else {
        int idx = (k - 75) * 256 + tid;    // 0 .. 192*128-1
        int kk = idx >> 7, j = idx & 127;
        int c = j >> 1;
        g_wi[idx] = (j & 1) ? W5[kk * 64 + c] : W2[kk * 64 + c];
    }
}

// ============================================================================
// K0b: counting sort of rows by u_items_mask, DESCENDING. Also resets g_ctr.
// ============================================================================
__global__ void k_sort(const int* __restrict__ mask) {
    __shared__ int cnt[64], off[64];
    int tid = threadIdx.x;
    if (tid < 64) cnt[tid] = 0;
    __syncthreads();
    for (int i = tid; i < B_; i += 1024) atomicAdd(&cnt[mask[i]], 1);
    __syncthreads();
    if (tid == 0) {
        g_ctr = 0;
        int run = 0;
        for (int m = 50; m >= 1; m--) { off[m] = run; run += cnt[m]; }
    }
    __syncthreads();
    if (tid < 64) cnt[tid] = 0;
    __syncthreads();
    for (int i = tid; i < B_; i += 1024) {
        int m = mask[i];
        int pos = off[m] + atomicAdd(&cnt[m], 1);
        g_order[pos] = i;
    }
}

// ============================================================================
// K1: g_ju1 = x74 @ Wc + bc, g_jv = x74 @ W3 + b3. (unchanged, validated)
// ============================================================================
#define PRE_SMEM (32 * 76 * 4)

__global__ void __launch_bounds__(256)
k_precompute(const float* __restrict__ item_emb, const float* __restrict__ i_class,
             const float* __restrict__ W3, const float* __restrict__ b3) {
    extern __shared__ float sm[];
    float* xs = sm;                  // 32*76

    int tid = threadIdx.x;
    int c = tid & 31, rgrp = tid >> 5;
    int row0 = blockIdx.x * 32;
    for (int i = tid; i < 32 * 74; i += 256) {
        int rr = i / 74, k = i % 74;
        int row = row0 + rr;
        float v = 0.f;
        if (row < NIP1) v = (k < 64) ? item_emb[row * 64 + k] : i_class[row * 10 + (k - 64)];
        xs[rr * 76 + k] = v;
    }
    __syncthreads();

    ull a[4][4], jv[4];
    {
        const ull* bp = (const ull*)&g_bc[8 * c];
        ull b0 = __ldg(bp), b1v = __ldg(bp + 1), b2v = __ldg(bp + 2), b3v = __ldg(bp + 3);
        ull jb = __ldg((const ull*)&b3[2 * c]);
#pragma unroll
        for (int r = 0; r < 4; r++) {
            a[r][0] = b0; a[r][1] = b1v; a[r][2] = b2v; a[r][3] = b3v;
            jv[r] = jb;
        }
    }
#pragma unroll 2
    for (int k = 0; k < 74; k++) {
        const ulonglong2* wp = (const ulonglong2*)&g_wc[k * 256 + 8 * c];
        ulonglong2 wa = __ldg(wp), wb = __ldg(wp + 1);
        ull w3v = __ldg((const ull*)&W3[k * 64 + 2 * c]);
#pragma unroll
        for (int r = 0; r < 4; r++) {
            float av = xs[(rgrp * 4 + r) * 76 + k];
            ull ad; PACK_DUP(ad, av);
            FMA2(a[r][0], ad, wa.x, a[r][0]);
            FMA2(a[r][1], ad, wa.y, a[r][1]);
            FMA2(a[r][2], ad, wb.x, a[r][2]);
            FMA2(a[r][3], ad, wb.y, a[r][3]);
            FMA2(jv[r], ad, w3v, jv[r]);
        }
    }
#pragma unroll
    for (int r = 0; r < 4; r++) {
        int row = row0 + rgrp * 4 + r;
        if (row < NIP1) {
            ull* o = (ull*)&g_ju1[row * 256 + 8 * c];
            o[0] = a[r][0]; o[1] = a[r][1]; o[2] = a[r][2]; o[3] = a[r][3];
            *(ull*)&g_jv[row * 64 + 2 * c] = jv[r];
        }
    }
}

// ============================================================================
// K2: WARP-AUTONOMOUS LSTM. Each warp owns a 4-row chunk (all 64 cells:
// thread lane -> cells {2*lane, 2*lane+1}). h lives in a warp-private smem
// double buffer -> no __syncthreads in the time loop, only __syncwarp.
// Static banded chunk assignment: chunk = band*148 + blockIdx; bands ordered
// so the longest chunks (band 0) share their SMSP with the empty band 7.
// Smem weight layout (conflict-free LDS.128):
//   Wp[k][half*128 + lane*4 + g] = Whh[k][(2*lane+half) + 64*g]
// Warp h layout: hbuf[k][r] (k stride 4 floats) -> one LDS.128 broadcast/k.
// ============================================================================
#define LSTM_WFL (2*64*4 + 200)    // floats per warp region (hbuf x2 + idxs)
#define LSTM_SMEM ((64*256 + 8*LSTM_WFL) * 4)

__global__ void __launch_bounds__(256, 1)
k_lstm(const int* __restrict__ u_items, const int* __restrict__ u_items_mask,
       const float* __restrict__ Whh) {
    extern __shared__ float sm[];
    float* Wp = sm;                               // 64*256
    int wid = threadIdx.x >> 5, lane = threadIdx.x & 31;
    float* hbuf = Wp + 64 * 256 + wid * LSTM_WFL; // 2 x 64x4
    int*   idxs = (int*)(hbuf + 2 * 64 * 4);      // 4*50

    // stage permuted Whh (even cells first half, odd cells second half)
    for (int i = threadIdx.x; i < 64 * 256; i += 256) {
        int k = i >> 8, jp = i & 255;
        int half = jp >> 7, rem = jp & 127;
        int l = rem >> 2, g = rem & 3;
        Wp[i] = Whh[k * 256 + (2 * l + half) + 64 * g];
    }
    __syncthreads();   // the only block-wide barrier

    int band = (wid < 4) ? wid : (11 - wid);      // pairs SMSP: (0,7)(1,6)(2,5)(3,4)
    int chunk = band * 148 + blockIdx.x;
    if (chunk >= 1024) return;

    int rows[4], msk[4];
#pragma unroll
    for (int r = 0; r < 4; r++) {
        rows[r] = g_order[chunk * 4 + r];
        msk[r] = u_items_mask[rows[r]];
    }
    int maxm = msk[0];    // sorted desc -> first is max

    for (int i = lane; i < 4 * 50; i += 32) {
        int r = i / 50, t = i - r * 50;
        idxs[i] = u_items[rows[r] * 50 + t];
    }
    for (int i = lane; i < 64 * 4; i += 32) hbuf[i] = 0.f;   // h_{-1} = 0
    __syncwarp();

    float c_reg[2][4];
#pragma unroll
    for (int c = 0; c < 2; c++)
#pragma unroll
        for (int r = 0; r < 4; r++) c_reg[c][r] = 0.f;

    // prefetch x-part (cells 2l,2l+1 = 8 floats at offset 8*lane) for t=0
    float4 p[4][2];
#pragma unroll
    for (int r = 0; r < 4; r++) {
        const float4* src = (const float4*)&g_ju1[idxs[r * 50] * 256 + lane * 8];
        p[r][0] = src[0]; p[r][1] = src[1];
    }

    for (int t = 0; t < maxm; t++) {
        const float* hr = hbuf + (t & 1) * 256;
        float* hw = hbuf + ((t + 1) & 1) * 256;

        // init acc[cell][gate][rowpair] from prefetched x-part
        ull acc[2][4][2];
#pragma unroll
        for (int c = 0; c < 2; c++) {
            PACK2(acc[c][0][0], p[0][c].x, p[1][c].x);
            PACK2(acc[c][1][0], p[0][c].y, p[1][c].y);
            PACK2(acc[c][2][0], p[0][c].z, p[1][c].z);
            PACK2(acc[c][3][0], p[0][c].w, p[1][c].w);
            PACK2(acc[c][0][1], p[2][c].x, p[3][c].x);
            PACK2(acc[c][1][1], p[2][c].y, p[3][c].y);
            PACK2(acc[c][2][1], p[2][c].z, p[3][c].z);
            PACK2(acc[c][3][1], p[2][c].w, p[3][c].w);
        }
        if (t + 1 < maxm) {
#pragma unroll
            for (int r = 0; r < 4; r++) {
                const float4* src = (const float4*)&g_ju1[idxs[r * 50 + t + 1] * 256 + lane * 8];
                p[r][0] = src[0]; p[r][1] = src[1];
            }
        }

        // h @ Whh for 4 rows x 2 cells
#pragma unroll 4
        for (int k = 0; k < 64; k++) {
            float4 wA = *(const float4*)&Wp[k * 256 + lane * 4];        // cell 2l
            float4 wB = *(const float4*)&Wp[k * 256 + 128 + lane * 4];  // cell 2l+1
            ulonglong2 hp = *(const ulonglong2*)&hr[k * 4];             // rows 0-3
            ull d;
            PACK_DUP(d, wA.x); FMA2(acc[0][0][0], hp.x, d, acc[0][0][0]); FMA2(acc[0][0][1], hp.y, d, acc[0][0][1]);
            PACK_DUP(d, wA.y); FMA2(acc[0][1][0], hp.x, d, acc[0][1][0]); FMA2(acc[0][1][1], hp.y, d, acc[0][1][1]);
            PACK_DUP(d, wA.z); FMA2(acc[0][2][0], hp.x, d, acc[0][2][0]); FMA2(acc[0][2][1], hp.y, d, acc[0][2][1]);
            PACK_DUP(d, wA.w); FMA2(acc[0][3][0], hp.x, d, acc[0][3][0]); FMA2(acc[0][3][1], hp.y, d, acc[0][3][1]);
            PACK_DUP(d, wB.x); FMA2(acc[1][0][0], hp.x, d, acc[1][0][0]); FMA2(acc[1][0][1], hp.y, d, acc[1][0][1]);
            PACK_DUP(d, wB.y); FMA2(acc[1][1][0], hp.x, d, acc[1][1][0]); FMA2(acc[1][1][1], hp.y, d, acc[1][1][1]);
            PACK_DUP(d, wB.z); FMA2(acc[1][2][0], hp.x, d, acc[1][2][0]); FMA2(acc[1][2][1], hp.y, d, acc[1][2][1]);
            PACK_DUP(d, wB.w); FMA2(acc[1][3][0], hp.x, d, acc[1][3][0]); FMA2(acc[1][3][1], hp.y, d, acc[1][3][1]);
        }

        // epilogue: gates -> c,h ; h to warp-private buffer
        float hval[2][4];
#pragma unroll
        for (int c = 0; c < 2; c++) {
#pragma unroll
            for (int pr = 0; pr < 2; pr++) {
                float gi0, gi1, gf0, gf1, gg0, gg1, go0, go1;
                UNPACK2(gi0, gi1, acc[c][0][pr]);
                UNPACK2(gf0, gf1, acc[c][1][pr]);
                UNPACK2(gg0, gg1, acc[c][2][pr]);
                UNPACK2(go0, go1, acc[c][3][pr]);
#pragma unroll
                for (int h2 = 0; h2 < 2; h2++) {
                    int r = 2 * pr + h2;
                    float gi = h2 ? gi1 : gi0;
                    float gf = h2 ? gf1 : gf0;
                    float gg = h2 ? gg1 : gg0;
                    float go = h2 ? go1 : go0;
                    float cc = sigf(gf) * c_reg[c][r] + sigf(gi) * tanhf_fast(gg);
                    c_reg[c][r] = cc;
                    hval[c][r] = sigf(go) * tanhf_fast(cc);
                }
                ull hp2; PACK2(hp2, hval[c][2 * pr], hval[c][2 * pr + 1]);
                *(ull*)&hw[(2 * lane + c) * 4 + 2 * pr] = hp2;
            }
        }
#pragma unroll
        for (int r = 0; r < 4; r++) {
            if (t == msk[r] - 1) {
                float2 o; o.x = hval[0][r]; o.y = hval[1][r];
                *(float2*)&g_hu[rows[r] * 64 + 2 * lane] = o;
            }
        }
        __syncwarp();
    }
}

// ============================================================================
// K3: per-row user stage (unchanged, validated).
// ============================================================================
#define USER_SMEM ((128 + 128 + 8*384) * 4)

__global__ void __launch_bounds__(256)
k_user(const int* __restrict__ users, const int* __restrict__ items,
       const int* __restrict__ u_frids, const int* __restrict__ u_frids_mask,
       const int* __restrict__ u_frids_items, const int* __restrict__ F_i,
       const float* __restrict__ user_emb, const float* __restrict__ item_emb,
       const float* __restrict__ b2,
       const float* __restrict__ W4, const float* __restrict__ b4,
       const float* __restrict__ b5,
       const float* __restrict__ W6, const float* __restrict__ b6,
       const float* __restrict__ lambdas) {
    extern __shared__ float sm[];
    float* W4s = sm;                 // 128
    float* W6s = W4s + 128;          // 128
    float* zz  = W6s + 128;          // 8 * 384

    int tid = threadIdx.x;
    if (tid < 128) W4s[tid] = W4[tid];
    else W6s[tid - 128] = W6[tid - 128];
    __syncthreads();

    int w = tid >> 5, lane = tid & 31;
    int row = blockIdx.x * 8 + w;
    int c0 = lane * 2;
    float l0 = lambdas[0], l1 = lambdas[1], l2 = lambdas[2], l3 = lambdas[3];
    float b4v = b4[0], b6v = b6[0];

    int usr = users[row], itm = items[row];
    float2 u2  = *(const float2*)(user_emb + usr * 64 + c0);
    float2 ie2 = *(const float2*)(item_emb + itm * 64 + c0);
    float2 hu2 = *(const float2*)(g_hu + row * 64 + c0);

    float px[K_], py[K_];
#pragma unroll
    for (int k = 0; k < K_; k++) { px[k] = 0.f; py[k] = 0.f; }
    const int* ip = u_frids_items + row * (K_ * LI_);
#pragma unroll
    for (int k = 0; k < K_; k++) {
#pragma unroll
        for (int li = 0; li < LI_; li++) {
            int idx = ip[k * LI_ + li];
            float2 j2 = *(const float2*)(g_jv + idx * 64 + c0);
            px[k] += j2.x; py[k] += j2.y;
        }
    }

    float du_p = u2.x * W4s[c0] + u2.y * W4s[c0 + 1];
    float at_p[K_];
#pragma unroll
    for (int k = 0; k < K_; k++) {
        int fid = u_frids[row * K_ + k];
        float2 v2 = *(const float2*)(user_emb + fid * 64 + c0);
        at_p[k] = v2.x * W4s[64 + c0] + v2.y * W4s[65 + c0];
    }
#pragma unroll
    for (int o = 16; o; o >>= 1) {
        du_p += __shfl_xor_sync(0xffffffffu, du_p, o);
#pragma unroll
        for (int k = 0; k < K_; k++) at_p[k] += __shfl_xor_sync(0xffffffffu, at_p[k], o);
    }
    int fm = u_frids_mask[row];
    float at[K_];
#pragma unroll
    for (int k = 0; k < K_; k++) at[k] = lrelu(du_p + at_p[k] + b4v);
    float mx = -1e30f;
#pragma unroll
    for (int k = 0; k < K_; k++) if (k < fm) mx = fmaxf(mx, at[k]);
    float se = 0.f, ev[K_];
#pragma unroll
    for (int k = 0; k < K_; k++) { ev[k] = (k < fm) ? expf(at[k] - mx) : 0.f; se += ev[k]; }
    float inv = 1.f / (se * (float)fm);

    float sux = 0.f, suy = 0.f;
#pragma unroll
    for (int k = 0; k < K_; k++) {
        float wk = ev[k] * inv;
        sux = fmaf(wk, px[k], sux);
        suy = fmaf(wk, py[k], suy);
    }

    ull* z = (ull*)(zz + w * 384);
    PACK2(z[c0],       hu2.x, sux);
    PACK2(z[c0 + 1],   hu2.y, suy);
    PACK2(z[64 + c0],     ie2.x, ie2.x);
    PACK2(z[64 + c0 + 1], ie2.y, ie2.y);
    PACK2(z[128 + c0],     hu2.x * ie2.x, sux * ie2.x);
    PACK2(z[128 + c0 + 1], hu2.y * ie2.y, suy * ie2.y);
    __syncwarp();
    ull acc0, acc1;
    PACK2(acc0, b2[c0], b5[c0]);
    PACK2(acc1, b2[c0 + 1], b5[c0 + 1]);
    const ulonglong2* wip = (const ulonglong2*)&g_wi[4 * lane];
#pragma unroll 8
    for (int k = 0; k < 192; k++) {
        ull zk = z[k];
        ulonglong2 wv = __ldg(wip + k * 32);
        FMA2(acc0, zk, wv.x, acc0);
        FMA2(acc1, zk, wv.y, acc1);
    }
    float huix, suix, huiy, suiy;
    UNPACK2(huix, suix, acc0);
    UNPACK2(huiy, suiy, acc1);

    float zsx = l0 * hu2.x + l1 * huix + l2 * sux + l3 * suix;
    float zsy = l0 * hu2.y + l1 * huiy + l2 * suy + l3 * suiy;

    float di_p = ie2.x * W6s[c0] + ie2.y * W6s[c0 + 1];
#pragma unroll
    for (int o = 16; o; o >>= 1) di_p += __shfl_xor_sync(0xffffffffu, di_p, o);

#pragma unroll
    for (int s = 0; s < 2; s++) {
        float sp[K_], dp[K_];
#pragma unroll
        for (int k = 0; k < K_; k++) {
            int fi = F_i[(row * 2 + s) * K_ + k];
            float2 f2 = *(const float2*)(item_emb + fi * 64 + c0);
            sp[k] = f2.x * W6s[64 + c0] + f2.y * W6s[65 + c0];
            dp[k] = f2.x * zsx + f2.y * zsy;
        }
#pragma unroll
        for (int o = 16; o; o >>= 1) {
#pragma unroll
            for (int k = 0; k < K_; k++) {
                sp[k] += __shfl_xor_sync(0xffffffffu, sp[k], o);
                dp[k] += __shfl_xor_sync(0xffffffffu, dp[k], o);
            }
        }
        if (lane == 0) {
            float* spo = s ? g_s2 : g_s1;
            float* dpo = s ? g_d2 : g_d1;
#pragma unroll
            for (int k = 0; k < K_; k++) {
                spo[k * B_ + row] = lrelu(di_p + sp[k] + b6v);
                dpo[k * B_ + row] = dp[k];
            }
        }
    }
}

// ============================================================================
// K4: per-column softmax stats (online), coalesced [K][B].
// ============================================================================
__global__ void k_cstat() {
    int sel = blockIdx.x / K_;
    int k = blockIdx.x % K_;
    const float* s = (sel ? g_s2 : g_s1) + k * B_;
    __shared__ float rm[1024], rs[1024];
    int tid = threadIdx.x;
    float m = -1e30f, acc = 0.f;
    for (int i = tid; i < B_; i += 1024) {
        float x = s[i];
        float nm = fmaxf(m, x);
        acc = acc * expf(m - nm) + expf(x - nm);
        m = nm;
    }
    rm[tid] = m; rs[tid] = acc;
    __syncthreads();
    for (int o = 512; o; o >>= 1) {
        if (tid < o) {
            float m2 = rm[tid + o], s2v = rs[tid + o];
            float nm = fmaxf(rm[tid], m2);
            rs[tid] = rs[tid] * expf(rm[tid] - nm) + s2v * expf(m2 - nm);
            rm[tid] = nm;
        }
        __syncthreads();
    }
    if (tid == 0) { g_cs[sel * 2 * K_ + k] = rm[0]; g_cs[sel * 2 * K_ + K_ + k] = rs[0]; }
}

// ============================================================================
// K5: final S + sigmoid (coalesced [K][B] reads)
// ============================================================================
__global__ void k_final(const float* __restrict__ alpha, float* __restrict__ out) {
    int b = blockIdx.x * 256 + threadIdx.x;
    float a = alpha[0];
    float S1 = 0.f, S2 = 0.f;
#pragma unroll
    for (int k = 0; k < K_; k++) {
        S1 += expf(g_s1[k * B_ + b] - g_cs[k]) / g_cs[K_ + k] * g_d1[k * B_ + b];
        S2 += expf(g_s2[k * B_ + b] - g_cs[2 * K_ + k]) / g_cs[3 * K_ + k] * g_d2[k * B_ + b];
    }
    float S = a * S1 + (1.f - a) * S2;
    out[b] = 1.f / (1.f + expf(-S));
}

// ============================================================================
extern "C" void kernel_launch(void* const* d_in, const int* in_sizes, int n_in,
                              void* d_out, int out_size) {
    const int*   users        = (const int*)d_in[0];
    const int*   items        = (const int*)d_in[1];
    const int*   u_items      = (const int*)d_in[2];
    const int*   u_items_mask = (const int*)d_in[3];
    const int*   u_frids      = (const int*)d_in[4];
    const int*   u_frids_mask = (const int*)d_in[5];
    const int*   u_frids_items= (const int*)d_in[6];
    const int*   F_i          = (const int*)d_in[7];
    const float* user_emb     = (const float*)d_in[8];
    const float* item_emb     = (const float*)d_in[9];
    const float* i_class      = (const float*)d_in[10];
    const float* W1  = (const float*)d_in[11];
    const float* b1  = (const float*)d_in[12];
    const float* Wih = (const float*)d_in[13];
    const float* Whh = (const float*)d_in[14];
    const float* bih = (const float*)d_in[15];
    const float* bhh = (const float*)d_in[16];
    const float* W2  = (const float*)d_in[17];
    const float* b2  = (const float*)d_in[18];
    const float* W3  = (const float*)d_in[19];
    const float* b3  = (const float*)d_in[20];
    const float* W4  = (const float*)d_in[21];
    const float* b4  = (const float*)d_in[22];
    const float* W5  = (const float*)d_in[23];
    const float* b5  = (const float*)d_in[24];
    const float* W6  = (const float*)d_in[25];
    const float* b6  = (const float*)d_in[26];
    const float* alpha   = (const float*)d_in[27];
    const float* lambdas = (const float*)d_in[28];

    cudaFuncSetAttribute(k_precompute, cudaFuncAttributeMaxDynamicSharedMemorySize, PRE_SMEM);
    cudaFuncSetAttribute(k_lstm, cudaFuncAttributeMaxDynamicSharedMemorySize, LSTM_SMEM);
    cudaFuncSetAttribute(k_user, cudaFuncAttributeMaxDynamicSharedMemorySize, USER_SMEM);

    k_combine<<<171, 256>>>(W1, b1, Wih, bih, bhh, W2, W5);
    k_sort<<<1, 1024>>>(u_items_mask);
    k_precompute<<<(NIP1 + 31) / 32, 256, PRE_SMEM>>>(item_emb, i_class, W3, b3);
    k_lstm<<<148, 256, LSTM_SMEM>>>(u_items, u_items_mask, Whh);
    k_user<<<B_ / 8, 256, USER_SMEM>>>(users, items, u_frids, u_frids_mask,
                                       u_frids_items, F_i, user_emb, item_emb,
                                       b2, W4, b4, b5, W6, b6, lambdas);
    k_cstat<<<2 * K_, 1024>>>();
    k_final<<<B_ / 256, 256>>>(alpha, (float*)d_out);
}